// round 4
// baseline (speedup 1.0000x reference)
#include <cuda_runtime.h>
#include <stdint.h>

// B = 1048576, D = 3, L = 16, C = 2, H = 16, S = 1.0
//   res(l) = 16 << l, side(l) = res+1
//   dense: l = 0,1,2 ; hashed: l >= 3 (hm = 2^19)
//   offsets: 0, 4920, 40864, 315496, then +524288/level (all even)
//   table = concat(ext[524288,2], own[.,2])
//
// R4 = R2 load structure (divergent pair-branch: LDG.128 when the x-corner
// pair occupies one aligned 16B slot, else 2x LDG.64) +
//   - level-0 table (4920 float2 = 39.4KB) staged in static smem; level-0
//     gathers become LDS, removing ~6% of l1tex global tag traffic.
//   - persistent grid-stride blocks (592 x 512) so the preload amortizes and
//     per-thread level l is loop-invariant (stride % 16 == 0) -> level
//     constants hoisted out of the loop.

#define HASH_SPLIT 524288u
#define P2 2654435761u
#define P3 805459861u

#define NTHREADS 512
#define NBLOCKS  592          // 148 SMs x 4 blocks
#define NITEMS   16777216u    // B * L
#define L0_SIZE  4920

__device__ __forceinline__ const float2* tptr(unsigned g,
                                              const float2* __restrict__ ext,
                                              const float2* __restrict__ own)
{
    return (g < HASH_SPLIT) ? (ext + g) : (own + (g - HASH_SPLIT));
}

__global__ void __launch_bounds__(NTHREADS, 4)
grid_encode_kernel(const float* __restrict__ pts,
                   const float2* __restrict__ ext,
                   const float2* __restrict__ own,
                   float2* __restrict__ out)
{
    __shared__ float2 s_tab[L0_SIZE];

    // Preload level-0 table (ext[0..4920)) into smem, coalesced.
    for (int i = threadIdx.x; i < L0_SIZE; i += NTHREADS)
        s_tab[i] = ext[i];
    __syncthreads();

    const unsigned tid0 = blockIdx.x * NTHREADS + threadIdx.x;
    const unsigned l = tid0 & 15u;           // loop-invariant: stride % 16 == 0

    // Hoisted per-level constants.
    const unsigned res  = 16u << l;
    const float scale   = (float)(res - 1u);
    const unsigned side = res + 1u;
    const unsigned side2 = side * side;
    const bool hashed = (l >= 3u);
    const bool lvl0   = (l == 0u);
    const unsigned off = hashed ? (315496u + (l - 3u) * 524288u)
                                : (l == 0u ? 0u : (l == 1u ? 4920u : 40864u));

    for (unsigned gtid = tid0; gtid < NITEMS; gtid += NBLOCKS * NTHREADS) {
        const unsigned b = gtid >> 4;

        const float px_in = __ldg(&pts[3u * b + 0u]);
        const float py_in = __ldg(&pts[3u * b + 1u]);
        const float pz_in = __ldg(&pts[3u * b + 2u]);

        const float posx = (px_in + 1.0f) * 0.5f * scale + 0.5f;
        const float posy = (py_in + 1.0f) * 0.5f * scale + 0.5f;
        const float posz = (pz_in + 1.0f) * 0.5f * scale + 0.5f;

        const float flx = floorf(posx);
        const float fly = floorf(posy);
        const float flz = floorf(posz);
        const float fx = posx - flx;
        const float fy = posy - fly;
        const float fz = posz - flz;
        const unsigned x0 = (unsigned)flx;
        const unsigned y0 = (unsigned)fly;
        const unsigned z0 = (unsigned)flz;

        const float wx0 = 1.0f - fx, wx1 = fx;
        const float wy[2] = { 1.0f - fy, fy };
        const float wz[2] = { 1.0f - fz, fz };

        float accx = 0.0f, accy = 0.0f;

        if (lvl0) {
            // Level 0: dense side=17, whole table in smem. idx <= 4912.
            const unsigned base0 = x0 + y0 * 17u + z0 * 289u;
#pragma unroll
            for (int p = 0; p < 4; ++p) {
                const int cy = p & 1, cz = (p >> 1) & 1;
                const unsigned ix = base0 + (unsigned)cy * 17u + (unsigned)cz * 289u;
                const float2 va = s_tab[ix];
                const float2 vb = s_tab[ix + 1u];
                const float wyz = wy[cy] * wz[cz];
                accx += wyz * (wx0 * va.x + wx1 * vb.x);
                accy += wyz * (wx0 * va.y + wx1 * vb.y);
            }
        } else {
            // Hash per-axis terms (uint32 wraparound; PRIMES = {1, P2, P3})
            const unsigned hy0 = y0 * P2;
            const unsigned hz0 = z0 * P3;
            const unsigned hys[2] = { hy0, hy0 + P2 };
            const unsigned hzs[2] = { hz0, hz0 + P3 };
            // Dense per-axis terms (no modulo: side^3 <= hm for l<=2)
            const unsigned dys[2] = { y0 * side,  y0 * side + side };
            const unsigned dzs[2] = { z0 * side2, z0 * side2 + side2 };

            unsigned ia[4], ib[4];
#pragma unroll
            for (int p = 0; p < 4; ++p) {
                const int cy = p & 1, cz = (p >> 1) & 1;
                unsigned a, bx;
                if (hashed) {
                    const unsigned base = hys[cy] ^ hzs[cz];
                    a  = (x0 ^ base) & (HASH_SPLIT - 1u);
                    bx = ((x0 + 1u) ^ base) & (HASH_SPLIT - 1u);
                } else {
                    const unsigned base = dys[cy] + dzs[cz];
                    a  = x0 + base;
                    bx = a + 1u;
                }
                ia[p] = off + a;
                ib[p] = off + bx;
            }

            // R2 fetch: one aligned LDG.128 when pair shares a 16B slot,
            // else two LDG.64. Pair never crosses level/half boundaries
            // (all even).
            float2 v0[4], v1[4];
#pragma unroll
            for (int p = 0; p < 4; ++p) {
                const unsigned a = ia[p], bb = ib[p];
                if ((a ^ bb) == 1u) {
                    const unsigned lo = a & ~1u;
                    const float4 w4 = __ldg((const float4*)tptr(lo, ext, own));
                    const bool swap = (a & 1u);
                    v0[p] = swap ? make_float2(w4.z, w4.w) : make_float2(w4.x, w4.y);
                    v1[p] = swap ? make_float2(w4.x, w4.y) : make_float2(w4.z, w4.w);
                } else {
                    v0[p] = __ldg(tptr(a,  ext, own));
                    v1[p] = __ldg(tptr(bb, ext, own));
                }
            }

#pragma unroll
            for (int p = 0; p < 4; ++p) {
                const int cy = p & 1, cz = (p >> 1) & 1;
                const float wyz = wy[cy] * wz[cz];
                accx += wyz * (wx0 * v0[p].x + wx1 * v1[p].x);
                accy += wyz * (wx0 * v0[p].y + wx1 * v1[p].y);
            }
        }

        out[gtid] = make_float2(accx, accy);
    }
}

extern "C" void kernel_launch(void* const* d_in, const int* in_sizes, int n_in,
                              void* d_out, int out_size)
{
    const float*  pts = (const float*)d_in[0];        // [B, 3]
    const float2* ext = (const float2*)d_in[1];       // [524288, 2]
    const float2* own = (const float2*)d_in[2];       // [N_TABLE - 524288, 2]
    float2* out = (float2*)d_out;                     // [B*16] float2

    grid_encode_kernel<<<NBLOCKS, NTHREADS>>>(pts, ext, own, out);
}